// round 6
// baseline (speedup 1.0000x reference)
#include <cuda_runtime.h>

#define B_ 256
#define T_ 512
#define D_ 128
#define U_ 128
#define C_ 64
#define M_ (B_*T_)   // 131072 rows

__device__ float g_H[(size_t)M_ * U_];   // tanh(X@W1+b1)

typedef unsigned long long ull;

__device__ __forceinline__ ull pk2(float x, float y) {
    ull r; asm("mov.b64 %0, {%1,%2};" : "=l"(r) : "f"(x), "f"(y)); return r;
}
__device__ __forceinline__ void upk2(ull v, float& x, float& y) {
    asm("mov.b64 {%0,%1}, %2;" : "=f"(x), "=f"(y) : "l"(v));
}
__device__ __forceinline__ ull ffma2(ull a, ull b, ull c) {
    ull d; asm("fma.rn.f32x2 %0, %1, %2, %3;" : "=l"(d) : "l"(a), "l"(b), "l"(c)); return d;
}
__device__ __forceinline__ float tanh_fast(float x) {
    float y; asm("tanh.approx.f32 %0, %1;" : "=f"(y) : "f"(x)); return y;
}

// ---------------------------------------------------------------------------
// K1: H = tanh(X @ W1 + b1). Unchanged (measured 108us).
// ---------------------------------------------------------------------------
__global__ void __launch_bounds__(256, 2)
k1_in_gemm(const float* __restrict__ X, const float* __restrict__ W1,
           const float* __restrict__ b1)
{
    extern __shared__ float smem[];
    float2* Wp = (float2*)smem;            // [64][128] float2  (64 KB)
    float*  Xs = smem + 16384;             // [64][128] float   (32 KB)
    const int tid = threadIdx.x;
    const int m0 = blockIdx.x * 64;

    {
        const int c4 = (tid & 31) * 4;
        const int kp0 = tid >> 5;
        #pragma unroll
        for (int pass = 0; pass < 8; pass++) {
            int kp = kp0 + pass * 8;
            float4 a = *(const float4*)(W1 + (size_t)(2*kp)   * 128 + c4);
            float4 b = *(const float4*)(W1 + (size_t)(2*kp+1) * 128 + c4);
            float2* w = Wp + kp*128 + c4;
            w[0] = make_float2(a.x, b.x);
            w[1] = make_float2(a.y, b.y);
            w[2] = make_float2(a.z, b.z);
            w[3] = make_float2(a.w, b.w);
        }
    }
    {
        const int q  = (tid & 31) * 4;
        const int r0 = tid >> 5;
        #pragma unroll
        for (int pass = 0; pass < 8; pass++) {
            int row = r0 + pass * 8;
            *(float4*)(Xs + row*128 + q) =
                *(const float4*)(X + (size_t)(m0+row)*128 + q);
        }
    }
    __syncthreads();

    const int tc = tid & 31;
    const int tr = tid >> 5;
    ull acc[8][4];
    #pragma unroll
    for (int i = 0; i < 8; i++)
        #pragma unroll
        for (int c = 0; c < 4; c++) acc[i][c] = 0ULL;

    const float*  xbase = Xs + tr * 8 * 128;
    const float2* wbase = Wp + tc * 4;

    #pragma unroll 8
    for (int kp = 0; kp < 64; kp++) {
        ulonglong2 wv0 = *(const ulonglong2*)(wbase + (size_t)kp*128);
        ulonglong2 wv1 = *(const ulonglong2*)(wbase + (size_t)kp*128 + 2);
        #pragma unroll
        for (int i = 0; i < 8; i++) {
            ull xp = *(const ull*)(xbase + i*128 + 2*kp);
            acc[i][0] = ffma2(xp, wv0.x, acc[i][0]);
            acc[i][1] = ffma2(xp, wv0.y, acc[i][1]);
            acc[i][2] = ffma2(xp, wv1.x, acc[i][2]);
            acc[i][3] = ffma2(xp, wv1.y, acc[i][3]);
        }
    }

    float bb[4];
    #pragma unroll
    for (int c = 0; c < 4; c++) bb[c] = __ldg(b1 + tc*4 + c);

    #pragma unroll
    for (int i = 0; i < 8; i++) {
        int row = m0 + tr*8 + i;
        float4 o; float x, y;
        upk2(acc[i][0], x, y); o.x = tanh_fast(x + y + bb[0]);
        upk2(acc[i][1], x, y); o.y = tanh_fast(x + y + bb[1]);
        upk2(acc[i][2], x, y); o.z = tanh_fast(x + y + bb[2]);
        upk2(acc[i][3], x, y); o.w = tanh_fast(x + y + bb[3]);
        *(float4*)(g_H + (size_t)row*128 + tc*4) = o;
    }
}

// ---------------------------------------------------------------------------
// K2+K3 FUSED: recurrence + classifier head in the step's latency bubble.
// 128 CTAs x 256 thr; 2 chains (chain = tid>>7), column j = tid&127.
// W2[:,j] in registers (64 f32x2). State double-buffered in smem with a
// 16B pad between halves. Each step also computes out row t-1 from the
// state buffer being read anyway: thread -> (c = j>>1, uhalf q = j&1),
// Wc^T staged in smem (row stride 132, lane-rotated reads), partner
// reduction via shfl.xor(1). No g_F, no third kernel.
// ---------------------------------------------------------------------------
#define ST_SZ 132   // 64 | 4 pad | 64

__global__ void __launch_bounds__(256)
k2_fused(const float* __restrict__ W2, const float* __restrict__ b2,
         const float* __restrict__ Wc, const float* __restrict__ bc,
         float* __restrict__ out)
{
    __shared__ __align__(16) float st[2][2][ST_SZ];    // [chain][buf][*]
    __shared__ __align__(16) float WcT[64 * ST_SZ];    // WcT[c][u], 33KB

    const int tid   = threadIdx.x;
    const int chain = tid >> 7;
    const int j     = tid & 127;
    const int b     = blockIdx.x * 2 + chain;

    // stage Wc transposed: WcT[c][u] = Wc[u*64 + c]
    for (int idx = tid; idx < 64 * 128; idx += 256) {
        int c = idx >> 7, u = idx & 127;
        WcT[c * ST_SZ + u] = __ldg(Wc + (size_t)u * 64 + c);
    }

    // W2 column j in registers (64 f32x2)
    ull w[64];
    #pragma unroll
    for (int p = 0; p < 64; p++)
        w[p] = pk2(__ldg(W2 + (size_t)(2*p)*128 + j),
                   __ldg(W2 + (size_t)(2*p+1)*128 + j));
    const float b2v = __ldg(b2 + j);

    const int c = j >> 1;          // output class column
    const int q = j & 1;           // u-half for the head dot
    const float bcv = __ldg(bc + c);
    const float* wct = WcT + c * ST_SZ + q * 64;   // my 64 Wc^T values
    const int rot = j & 15;        // 16B-unit rotation (bank spread)

    const int sidx = (j & 63) + (j >> 6) * 68;     // state slot (pad-aware)
    st[chain][0][sidx] = 0.0f;
    st[chain][1][sidx] = 0.0f;
    __syncthreads();

    const float* Hp   = g_H + (size_t)b * (T_*128) + j;
    float*       outp = out + (size_t)b * (T_*64) + c;

    float h0 = Hp[0];
    float h1 = Hp[128];

    int buf = 0;
    #pragma unroll 1
    for (int t = 0; t < T_; t += 2) {
        #pragma unroll
        for (int u = 0; u < 2; u++) {
            float hv = u ? h1 : h0;
            int tp = t + u + 2;
            float hn = 0.0f;
            if (tp < T_) hn = Hp[(size_t)tp * 128];
            if (u) h1 = hn; else h0 = hn;

            const float* sb = st[chain][buf];

            // ---- recurrence dot: full 128-state x W2[:,j] ----
            ull a0 = 0ULL, a1 = 0ULL, a2 = 0ULL, a3 = 0ULL;
            #pragma unroll
            for (int p = 0; p < 8; p++) {
                ulonglong2 s0 = *(const ulonglong2*)(sb + 8*p);        // half0
                ulonglong2 s1 = *(const ulonglong2*)(sb + 68 + 8*p);   // half1
                a0 = ffma2(s0.x, w[4*p+0],  a0);
                a1 = ffma2(s0.y, w[4*p+1],  a1);
                a2 = ffma2(s1.x, w[32+4*p], a2);
                a3 = ffma2(s1.y, w[33+4*p], a3);
                ulonglong2 s0b = *(const ulonglong2*)(sb + 8*p + 4);
                ulonglong2 s1b = *(const ulonglong2*)(sb + 68 + 8*p + 4);
                a0 = ffma2(s0b.x, w[4*p+2],  a0);
                a1 = ffma2(s0b.y, w[4*p+3],  a1);
                a2 = ffma2(s1b.x, w[34+4*p], a2);
                a3 = ffma2(s1b.y, w[35+4*p], a3);
            }
            float x0,y0,x1,y1,x2,y2,x3,y3;
            upk2(a0,x0,y0); upk2(a1,x1,y1); upk2(a2,x2,y2); upk2(a3,x3,y3);
            float s = ((x0+y0)+(x1+y1)) + ((x2+y2)+(x3+y3)) + b2v;
            float yv = hv + tanh_fast(s);

            // ---- head dot: out row (t+u-1) from the same (old) state ----
            {
                ull c0 = 0ULL, c1 = 0ULL, c2 = 0ULL, c3 = 0ULL;
                const float* yp = sb + q * 68;
                #pragma unroll
                for (int i = 0; i < 8; i++) {
                    int i0 = (2*i     + rot) & 15;   // rotated 16B units
                    int i1 = (2*i + 1 + rot) & 15;
                    ulonglong2 wv0 = *(const ulonglong2*)(wct + 4*i0);
                    ulonglong2 sv0 = *(const ulonglong2*)(yp  + 4*i0);
                    ulonglong2 wv1 = *(const ulonglong2*)(wct + 4*i1);
                    ulonglong2 sv1 = *(const ulonglong2*)(yp  + 4*i1);
                    c0 = ffma2(sv0.x, wv0.x, c0);
                    c1 = ffma2(sv0.y, wv0.y, c1);
                    c2 = ffma2(sv1.x, wv1.x, c2);
                    c3 = ffma2(sv1.y, wv1.y, c3);
                }
                upk2(c0,x0,y0); upk2(c1,x1,y1); upk2(c2,x2,y2); upk2(c3,x3,y3);
                float part = ((x0+y0)+(x1+y1)) + ((x2+y2)+(x3+y3));
                part += __shfl_xor_sync(0xffffffffu, part, 1);
                int to = t + u - 1;
                if (q == 0 && to >= 0)
                    outp[(size_t)to * 64] = part + bcv;
            }

            // publish new state, advance
            st[chain][buf^1][sidx] = yv;
            asm volatile("bar.sync %0, 128;" :: "r"(chain + 1) : "memory");
            buf ^= 1;
        }
    }

    // tail: out row T-1 from final state (now in st[chain][buf])
    {
        const float* sb = st[chain][buf];
        const float* yp = sb + q * 68;
        ull c0 = 0ULL, c1 = 0ULL, c2 = 0ULL, c3 = 0ULL;
        #pragma unroll
        for (int i = 0; i < 8; i++) {
            int i0 = (2*i     + rot) & 15;
            int i1 = (2*i + 1 + rot) & 15;
            ulonglong2 wv0 = *(const ulonglong2*)(wct + 4*i0);
            ulonglong2 sv0 = *(const ulonglong2*)(yp  + 4*i0);
            ulonglong2 wv1 = *(const ulonglong2*)(wct + 4*i1);
            ulonglong2 sv1 = *(const ulonglong2*)(yp  + 4*i1);
            c0 = ffma2(sv0.x, wv0.x, c0);
            c1 = ffma2(sv0.y, wv0.y, c1);
            c2 = ffma2(sv1.x, wv1.x, c2);
            c3 = ffma2(sv1.y, wv1.y, c3);
        }
        float x0,y0,x1,y1,x2,y2,x3,y3;
        upk2(c0,x0,y0); upk2(c1,x1,y1); upk2(c2,x2,y2); upk2(c3,x3,y3);
        float part = ((x0+y0)+(x1+y1)) + ((x2+y2)+(x3+y3));
        part += __shfl_xor_sync(0xffffffffu, part, 1);
        if (q == 0)
            outp[(size_t)(T_-1) * 64] = part + bcv;
    }
}

extern "C" void kernel_launch(void* const* d_in, const int* in_sizes, int n_in,
                              void* d_out, int out_size) {
    (void)in_sizes; (void)n_in; (void)out_size;
    const float* X  = (const float*)d_in[0];
    const float* W1 = (const float*)d_in[1];
    const float* b1 = (const float*)d_in[2];
    const float* W2 = (const float*)d_in[3];
    const float* b2 = (const float*)d_in[4];
    const float* Wc = (const float*)d_in[5];
    const float* bc = (const float*)d_in[6];
    float* out = (float*)d_out;

    cudaFuncSetAttribute(k1_in_gemm, cudaFuncAttributeMaxDynamicSharedMemorySize, 98304);

    k1_in_gemm<<<M_/64, 256, 98304>>>(X, W1, b1);
    k2_fused<<<B_/2, 256>>>(W2, b2, Wc, bc, out);
}

// round 7
// speedup vs baseline: 1.8578x; 1.8578x over previous
#include <cuda_runtime.h>

#define B_ 256
#define T_ 512
#define D_ 128
#define U_ 128
#define C_ 64
#define M_ (B_*T_)   // 131072 rows

__device__ float g_H[(size_t)M_ * U_];   // tanh(X@W1+b1)

typedef unsigned long long ull;

__device__ __forceinline__ ull pk2(float x, float y) {
    ull r; asm("mov.b64 %0, {%1,%2};" : "=l"(r) : "f"(x), "f"(y)); return r;
}
__device__ __forceinline__ void upk2(ull v, float& x, float& y) {
    asm("mov.b64 {%0,%1}, %2;" : "=f"(x), "=f"(y) : "l"(v));
}
__device__ __forceinline__ ull ffma2(ull a, ull b, ull c) {
    ull d; asm("fma.rn.f32x2 %0, %1, %2, %3;" : "=l"(d) : "l"(a), "l"(b), "l"(c)); return d;
}
__device__ __forceinline__ float tanh_fast(float x) {
    float y; asm("tanh.approx.f32 %0, %1;" : "=f"(y) : "f"(x)); return y;
}

// ---------------------------------------------------------------------------
// K1: H = tanh(X @ W1 + b1). Unchanged (measured 108us, fma 51%).
// ---------------------------------------------------------------------------
__global__ void __launch_bounds__(256, 2)
k1_in_gemm(const float* __restrict__ X, const float* __restrict__ W1,
           const float* __restrict__ b1)
{
    extern __shared__ float smem[];
    float2* Wp = (float2*)smem;            // [64][128] float2  (64 KB)
    float*  Xs = smem + 16384;             // [64][128] float   (32 KB)
    const int tid = threadIdx.x;
    const int m0 = blockIdx.x * 64;

    {
        const int c4 = (tid & 31) * 4;
        const int kp0 = tid >> 5;
        #pragma unroll
        for (int pass = 0; pass < 8; pass++) {
            int kp = kp0 + pass * 8;
            float4 a = *(const float4*)(W1 + (size_t)(2*kp)   * 128 + c4);
            float4 b = *(const float4*)(W1 + (size_t)(2*kp+1) * 128 + c4);
            float2* w = Wp + kp*128 + c4;
            w[0] = make_float2(a.x, b.x);
            w[1] = make_float2(a.y, b.y);
            w[2] = make_float2(a.z, b.z);
            w[3] = make_float2(a.w, b.w);
        }
    }
    {
        const int q  = (tid & 31) * 4;
        const int r0 = tid >> 5;
        #pragma unroll
        for (int pass = 0; pass < 8; pass++) {
            int row = r0 + pass * 8;
            *(float4*)(Xs + row*128 + q) =
                *(const float4*)(X + (size_t)(m0+row)*128 + q);
        }
    }
    __syncthreads();

    const int tc = tid & 31;
    const int tr = tid >> 5;
    ull acc[8][4];
    #pragma unroll
    for (int i = 0; i < 8; i++)
        #pragma unroll
        for (int c = 0; c < 4; c++) acc[i][c] = 0ULL;

    const float*  xbase = Xs + tr * 8 * 128;
    const float2* wbase = Wp + tc * 4;

    #pragma unroll 8
    for (int kp = 0; kp < 64; kp++) {
        ulonglong2 wv0 = *(const ulonglong2*)(wbase + (size_t)kp*128);
        ulonglong2 wv1 = *(const ulonglong2*)(wbase + (size_t)kp*128 + 2);
        #pragma unroll
        for (int i = 0; i < 8; i++) {
            ull xp = *(const ull*)(xbase + i*128 + 2*kp);
            acc[i][0] = ffma2(xp, wv0.x, acc[i][0]);
            acc[i][1] = ffma2(xp, wv0.y, acc[i][1]);
            acc[i][2] = ffma2(xp, wv1.x, acc[i][2]);
            acc[i][3] = ffma2(xp, wv1.y, acc[i][3]);
        }
    }

    float bb[4];
    #pragma unroll
    for (int c = 0; c < 4; c++) bb[c] = __ldg(b1 + tc*4 + c);

    #pragma unroll
    for (int i = 0; i < 8; i++) {
        int row = m0 + tr*8 + i;
        float4 o; float x, y;
        upk2(acc[i][0], x, y); o.x = tanh_fast(x + y + bb[0]);
        upk2(acc[i][1], x, y); o.y = tanh_fast(x + y + bb[1]);
        upk2(acc[i][2], x, y); o.z = tanh_fast(x + y + bb[2]);
        upk2(acc[i][3], x, y); o.w = tanh_fast(x + y + bb[3]);
        *(float4*)(g_H + (size_t)row*128 + tc*4) = o;
    }
}

// ---------------------------------------------------------------------------
// K2 FUSED v2: recurrence + head, no spill.
// 128 CTAs x 256 thr; 2 chains/CTA (chain = tid>>7), column j = tid&127.
// W2[:,j] in regs (64 f32x2 = 128 regs). y-history: 16-deep smem ring
// (slot = t&15, padded rows). Every 16 steps the chain's 128 threads run a
// [16x128]@Wc[128x64] mini-GEMM from the ring -> out (head acc: 16 regs only;
// Wc pair-interleaved in smem). H prefetched 8 steps ahead in a register ring.
// ---------------------------------------------------------------------------
#define ST_ROW 136   // floats per history row: 64 | pad | 64 (halves at 0, 68)

__global__ void __launch_bounds__(256)
k2_fused(const float* __restrict__ W2, const float* __restrict__ b2,
         const float* __restrict__ Wc, const float* __restrict__ bc,
         float* __restrict__ out)
{
    extern __shared__ float sm[];
    float2* WcP  = (float2*)sm;          // [64 kp][64 c] float2 = 32KB
    float*  hist = sm + 8192;            // [2][16][ST_ROW] = 17.4KB

    const int tid   = threadIdx.x;
    const int chain = tid >> 7;
    const int j     = tid & 127;
    const int b     = blockIdx.x * 2 + chain;

    // stage Wc pair-interleaved over k: WcP[kp][c] = (Wc[2kp][c], Wc[2kp+1][c])
    for (int idx = tid; idx < 64 * 64; idx += 256) {
        int kp = idx >> 6, c = idx & 63;
        WcP[kp * 64 + c] = make_float2(__ldg(Wc + (size_t)(2*kp)   * 64 + c),
                                       __ldg(Wc + (size_t)(2*kp+1) * 64 + c));
    }

    // W2 column j in registers
    ull w[64];
    #pragma unroll
    for (int p = 0; p < 64; p++)
        w[p] = pk2(__ldg(W2 + (size_t)(2*p)*128 + j),
                   __ldg(W2 + (size_t)(2*p+1)*128 + j));
    const float b2v = __ldg(b2 + j);

    // head-GEMM thread mapping: rows r0,r0+1 (of 16), cols c4..c4+3 (of 64)
    const int r0 = (j >> 4) * 2;
    const int c4 = (j & 15) * 4;
    float bb[4];
    #pragma unroll
    for (int c = 0; c < 4; c++) bb[c] = __ldg(bc + c4 + c);

    float* myhist = hist + chain * (16 * ST_ROW);
    const int sidx = (j & 63) + (j >> 6) * 68;     // pad-aware slot index

    myhist[15 * ST_ROW + sidx] = 0.0f;             // y_{-1} = 0 (read by t=0)
    __syncthreads();

    const float* Hp = g_H + (size_t)b * (T_*128) + j;

    // H prefetch ring, 8 deep
    float hr[8];
    #pragma unroll
    for (int i = 0; i < 8; i++) hr[i] = Hp[(size_t)i * 128];

    #pragma unroll 1
    for (int t0 = 0; t0 < T_; t0 += 16) {
        #pragma unroll
        for (int u = 0; u < 16; u++) {
            float hv = hr[u & 7];
            int tp = t0 + u + 8;
            float hn = 0.0f;
            if (tp < T_) hn = Hp[(size_t)tp * 128];
            hr[u & 7] = hn;

            const float* sb = myhist + ((u + 15) & 15) * ST_ROW;
            ull a0 = 0ULL, a1 = 0ULL, a2 = 0ULL, a3 = 0ULL;
            #pragma unroll
            for (int p = 0; p < 8; p++) {
                ulonglong2 s0  = *(const ulonglong2*)(sb + 8*p);
                ulonglong2 s1  = *(const ulonglong2*)(sb + 68 + 8*p);
                a0 = ffma2(s0.x,  w[4*p+0],  a0);
                a1 = ffma2(s0.y,  w[4*p+1],  a1);
                a2 = ffma2(s1.x,  w[32+4*p], a2);
                a3 = ffma2(s1.y,  w[33+4*p], a3);
                ulonglong2 s0b = *(const ulonglong2*)(sb + 8*p + 4);
                ulonglong2 s1b = *(const ulonglong2*)(sb + 68 + 8*p + 4);
                a0 = ffma2(s0b.x, w[4*p+2],  a0);
                a1 = ffma2(s0b.y, w[4*p+3],  a1);
                a2 = ffma2(s1b.x, w[34+4*p], a2);
                a3 = ffma2(s1b.y, w[35+4*p], a3);
            }
            float x0,y0,x1,y1,x2,y2,x3,y3;
            upk2(a0,x0,y0); upk2(a1,x1,y1); upk2(a2,x2,y2); upk2(a3,x3,y3);
            float s = ((x0+y0)+(x1+y1)) + ((x2+y2)+(x3+y3)) + b2v;
            float yv = hv + tanh_fast(s);

            myhist[u * ST_ROW + sidx] = yv;        // slot u holds y_{t0+u}
            asm volatile("bar.sync %0, 128;" :: "r"(chain + 1) : "memory");
        }

        // ---- head mini-GEMM: out[t0+r][c] = sum_u y[t0+r][u] * Wc[u][c] ----
        {
            ull acc[2][4];
            #pragma unroll
            for (int r = 0; r < 2; r++)
                #pragma unroll
                for (int c = 0; c < 4; c++) acc[r][c] = 0ULL;

            const float* y0p = myhist + r0 * ST_ROW;
            const float* y1p = myhist + (r0 + 1) * ST_ROW;

            #pragma unroll 4
            for (int kp = 0; kp < 32; kp++) {      // k-half 0: elements 2kp
                ull ya = *(const ull*)(y0p + 2*kp);
                ull yb = *(const ull*)(y1p + 2*kp);
                ulonglong2 wc0 = *(const ulonglong2*)(WcP + kp*64 + c4);
                ulonglong2 wc1 = *(const ulonglong2*)(WcP + kp*64 + c4 + 2);
                acc[0][0] = ffma2(ya, wc0.x, acc[0][0]);
                acc[0][1] = ffma2(ya, wc0.y, acc[0][1]);
                acc[0][2] = ffma2(ya, wc1.x, acc[0][2]);
                acc[0][3] = ffma2(ya, wc1.y, acc[0][3]);
                acc[1][0] = ffma2(yb, wc0.x, acc[1][0]);
                acc[1][1] = ffma2(yb, wc0.y, acc[1][1]);
                acc[1][2] = ffma2(yb, wc1.x, acc[1][2]);
                acc[1][3] = ffma2(yb, wc1.y, acc[1][3]);
            }
            #pragma unroll 4
            for (int kp = 32; kp < 64; kp++) {     // k-half 1: elements 68+2(kp-32)
                ull ya = *(const ull*)(y0p + 68 + 2*(kp-32));
                ull yb = *(const ull*)(y1p + 68 + 2*(kp-32));
                ulonglong2 wc0 = *(const ulonglong2*)(WcP + kp*64 + c4);
                ulonglong2 wc1 = *(const ulonglong2*)(WcP + kp*64 + c4 + 2);
                acc[0][0] = ffma2(ya, wc0.x, acc[0][0]);
                acc[0][1] = ffma2(ya, wc0.y, acc[0][1]);
                acc[0][2] = ffma2(ya, wc1.x, acc[0][2]);
                acc[0][3] = ffma2(ya, wc1.y, acc[0][3]);
                acc[1][0] = ffma2(yb, wc0.x, acc[1][0]);
                acc[1][1] = ffma2(yb, wc0.y, acc[1][1]);
                acc[1][2] = ffma2(yb, wc1.x, acc[1][2]);
                acc[1][3] = ffma2(yb, wc1.y, acc[1][3]);
            }

            #pragma unroll
            for (int r = 0; r < 2; r++) {
                float4 o; float x, y;
                upk2(acc[r][0], x, y); o.x = x + y + bb[0];
                upk2(acc[r][1], x, y); o.y = x + y + bb[1];
                upk2(acc[r][2], x, y); o.z = x + y + bb[2];
                upk2(acc[r][3], x, y); o.w = x + y + bb[3];
                *(float4*)(out + ((size_t)b * T_ + t0 + r0 + r) * 64 + c4) = o;
            }
            // ring slots must not be overwritten until all reads done
            asm volatile("bar.sync %0, 128;" :: "r"(chain + 1) : "memory");
        }
    }
}

extern "C" void kernel_launch(void* const* d_in, const int* in_sizes, int n_in,
                              void* d_out, int out_size) {
    (void)in_sizes; (void)n_in; (void)out_size;
    const float* X  = (const float*)d_in[0];
    const float* W1 = (const float*)d_in[1];
    const float* b1 = (const float*)d_in[2];
    const float* W2 = (const float*)d_in[3];
    const float* b2 = (const float*)d_in[4];
    const float* Wc = (const float*)d_in[5];
    const float* bc = (const float*)d_in[6];
    float* out = (float*)d_out;

    cudaFuncSetAttribute(k1_in_gemm, cudaFuncAttributeMaxDynamicSharedMemorySize, 98304);
    cudaFuncSetAttribute(k2_fused,   cudaFuncAttributeMaxDynamicSharedMemorySize, 65536);

    k1_in_gemm<<<M_/64, 256, 98304>>>(X, W1, b1);

    const int k2_smem = (8192 + 2*16*ST_ROW) * 4;   // WcP + history
    k2_fused<<<B_/2, 256, k2_smem>>>(W2, b2, Wc, bc, out);
}

// round 9
// speedup vs baseline: 1.9566x; 1.0532x over previous
#include <cuda_runtime.h>

#define B_ 256
#define T_ 512
#define D_ 128
#define U_ 128
#define C_ 64
#define M_ (B_*T_)   // 131072 rows

__device__ float g_H[(size_t)M_ * U_];   // tanh(X@W1+b1)

typedef unsigned long long ull;

__device__ __forceinline__ ull pk2(float x, float y) {
    ull r; asm("mov.b64 %0, {%1,%2};" : "=l"(r) : "f"(x), "f"(y)); return r;
}
__device__ __forceinline__ void upk2(ull v, float& x, float& y) {
    asm("mov.b64 {%0,%1}, %2;" : "=f"(x), "=f"(y) : "l"(v));
}
__device__ __forceinline__ ull ffma2(ull a, ull b, ull c) {
    ull d; asm("fma.rn.f32x2 %0, %1, %2, %3;" : "=l"(d) : "l"(a), "l"(b), "l"(c)); return d;
}
__device__ __forceinline__ float tanh_fast(float x) {
    float y; asm("tanh.approx.f32 %0, %1;" : "=f"(y) : "f"(x)); return y;
}

// ---------------------------------------------------------------------------
// K1: H = tanh(X @ W1 + b1). Unchanged (measured 108us, fma 51%).
// ---------------------------------------------------------------------------
__global__ void __launch_bounds__(256, 2)
k1_in_gemm(const float* __restrict__ X, const float* __restrict__ W1,
           const float* __restrict__ b1)
{
    extern __shared__ float smem[];
    float2* Wp = (float2*)smem;            // [64][128] float2  (64 KB)
    float*  Xs = smem + 16384;             // [64][128] float   (32 KB)
    const int tid = threadIdx.x;
    const int m0 = blockIdx.x * 64;

    {
        const int c4 = (tid & 31) * 4;
        const int kp0 = tid >> 5;
        #pragma unroll
        for (int pass = 0; pass < 8; pass++) {
            int kp = kp0 + pass * 8;
            float4 a = *(const float4*)(W1 + (size_t)(2*kp)   * 128 + c4);
            float4 b = *(const float4*)(W1 + (size_t)(2*kp+1) * 128 + c4);
            float2* w = Wp + kp*128 + c4;
            w[0] = make_float2(a.x, b.x);
            w[1] = make_float2(a.y, b.y);
            w[2] = make_float2(a.z, b.z);
            w[3] = make_float2(a.w, b.w);
        }
    }
    {
        const int q  = (tid & 31) * 4;
        const int r0 = tid >> 5;
        #pragma unroll
        for (int pass = 0; pass < 8; pass++) {
            int row = r0 + pass * 8;
            *(float4*)(Xs + row*128 + q) =
                *(const float4*)(X + (size_t)(m0+row)*128 + q);
        }
    }
    __syncthreads();

    const int tc = tid & 31;
    const int tr = tid >> 5;
    ull acc[8][4];
    #pragma unroll
    for (int i = 0; i < 8; i++)
        #pragma unroll
        for (int c = 0; c < 4; c++) acc[i][c] = 0ULL;

    const float*  xbase = Xs + tr * 8 * 128;
    const float2* wbase = Wp + tc * 4;

    #pragma unroll 8
    for (int kp = 0; kp < 64; kp++) {
        ulonglong2 wv0 = *(const ulonglong2*)(wbase + (size_t)kp*128);
        ulonglong2 wv1 = *(const ulonglong2*)(wbase + (size_t)kp*128 + 2);
        #pragma unroll
        for (int i = 0; i < 8; i++) {
            ull xp = *(const ull*)(xbase + i*128 + 2*kp);
            acc[i][0] = ffma2(xp, wv0.x, acc[i][0]);
            acc[i][1] = ffma2(xp, wv0.y, acc[i][1]);
            acc[i][2] = ffma2(xp, wv1.x, acc[i][2]);
            acc[i][3] = ffma2(xp, wv1.y, acc[i][3]);
        }
    }

    float bb[4];
    #pragma unroll
    for (int c = 0; c < 4; c++) bb[c] = __ldg(b1 + tc*4 + c);

    #pragma unroll
    for (int i = 0; i < 8; i++) {
        int row = m0 + tr*8 + i;
        float4 o; float x, y;
        upk2(acc[i][0], x, y); o.x = tanh_fast(x + y + bb[0]);
        upk2(acc[i][1], x, y); o.y = tanh_fast(x + y + bb[1]);
        upk2(acc[i][2], x, y); o.z = tanh_fast(x + y + bb[2]);
        upk2(acc[i][3], x, y); o.w = tanh_fast(x + y + bb[3]);
        *(float4*)(g_H + (size_t)row*128 + tc*4) = o;
    }
}

// ---------------------------------------------------------------------------
// K2 v3 (fixed): WARP-SPECIALIZED recurrence + head.
// 128 CTAs x 384 thr. Threads 0..255: two recurrence chains (W2[:,j] in regs,
// per-step named bars 1/2), writing y into a 32-deep history ring.
// Threads 256..383: head warps computing the previous 16-step block's
// y @ Wc + bc -> out, concurrently (one block behind). Block-boundary
// __syncthreads (33 total) is the only cross-role sync.
// ST_ROW = 136 floats = 544B = 34x16  (16B-aligned rows; halves at 0 and 68).
// ---------------------------------------------------------------------------
#define ST_ROW 136

__global__ void __launch_bounds__(384, 1)
k2_fused(const float* __restrict__ W2, const float* __restrict__ b2,
         const float* __restrict__ Wc, const float* __restrict__ bc,
         float* __restrict__ out)
{
    extern __shared__ float sm[];
    float2* WcP  = (float2*)sm;           // [64 kp][64 c] float2 = 32KB
    float*  hist = sm + 8192;             // [2][32][ST_ROW] = 34.8KB

    const int tid = threadIdx.x;

    // stage Wc pair-interleaved: WcP[kp][c] = (Wc[2kp][c], Wc[2kp+1][c])
    for (int idx = tid; idx < 64 * 64; idx += 384) {
        int kp = idx >> 6, c = idx & 63;
        WcP[kp * 64 + c] = make_float2(__ldg(Wc + (size_t)(2*kp)   * 64 + c),
                                       __ldg(Wc + (size_t)(2*kp+1) * 64 + c));
    }

    if (tid < 256) {
        // ================= RECURRENCE ROLE =================
        const int chain = tid >> 7;
        const int j     = tid & 127;
        const int b     = blockIdx.x * 2 + chain;

        ull w[64];
        #pragma unroll
        for (int p = 0; p < 64; p++)
            w[p] = pk2(__ldg(W2 + (size_t)(2*p)*128 + j),
                       __ldg(W2 + (size_t)(2*p+1)*128 + j));
        const float b2v = __ldg(b2 + j);

        float* myhist = hist + chain * (32 * ST_ROW);
        const int sidx = (j & 63) + (j >> 6) * 68;

        myhist[31 * ST_ROW + sidx] = 0.0f;    // y_{-1} (read at t=0)
        __syncthreads();                      // pairs with head init sync

        const float* Hp = g_H + (size_t)b * (T_*128) + j;
        float hr[4];
        #pragma unroll
        for (int i = 0; i < 4; i++) hr[i] = Hp[(size_t)i * 128];

        #pragma unroll 1
        for (int blk = 0; blk < 33; blk++) {
            if (blk < 32) {
                const int t0 = blk * 16;
                #pragma unroll
                for (int u = 0; u < 16; u++) {
                    float hv = hr[u & 3];
                    int tp = t0 + u + 4;
                    float hn = 0.0f;
                    if (tp < T_) hn = Hp[(size_t)tp * 128];
                    hr[u & 3] = hn;

                    const float* sb = myhist + (((t0 + u + 31) & 31) * ST_ROW);
                    ull a0 = 0ULL, a1 = 0ULL, a2 = 0ULL, a3 = 0ULL;
                    #pragma unroll
                    for (int p = 0; p < 8; p++) {
                        ulonglong2 s0  = *(const ulonglong2*)(sb + 8*p);
                        ulonglong2 s1  = *(const ulonglong2*)(sb + 68 + 8*p);
                        a0 = ffma2(s0.x,  w[4*p+0],  a0);
                        a1 = ffma2(s0.y,  w[4*p+1],  a1);
                        a2 = ffma2(s1.x,  w[32+4*p], a2);
                        a3 = ffma2(s1.y,  w[33+4*p], a3);
                        ulonglong2 s0b = *(const ulonglong2*)(sb + 8*p + 4);
                        ulonglong2 s1b = *(const ulonglong2*)(sb + 68 + 8*p + 4);
                        a0 = ffma2(s0b.x, w[4*p+2],  a0);
                        a1 = ffma2(s0b.y, w[4*p+3],  a1);
                        a2 = ffma2(s1b.x, w[34+4*p], a2);
                        a3 = ffma2(s1b.y, w[35+4*p], a3);
                    }
                    float x0,y0,x1,y1,x2,y2,x3,y3;
                    upk2(a0,x0,y0); upk2(a1,x1,y1);
                    upk2(a2,x2,y2); upk2(a3,x3,y3);
                    float s = ((x0+y0)+(x1+y1)) + ((x2+y2)+(x3+y3)) + b2v;
                    float yv = hv + tanh_fast(s);

                    myhist[((t0 + u) & 31) * ST_ROW + sidx] = yv;
                    asm volatile("bar.sync %0, 128;" :: "r"(chain + 1) : "memory");
                }
            }
            __syncthreads();   // block boundary (all 384)
        }
    } else {
        // ================= HEAD ROLE =================
        const int htid    = tid - 256;        // 0..127
        const int chain_h = htid >> 6;
        const int q       = htid & 63;
        const int r0      = (q >> 4) * 4;     // 4 rows of 16
        const int c4      = (q & 15) * 4;     // 4 cols of 64
        const int b       = blockIdx.x * 2 + chain_h;

        float bb[4];
        #pragma unroll
        for (int c = 0; c < 4; c++) bb[c] = __ldg(bc + c4 + c);

        const float* myhist = hist + chain_h * (32 * ST_ROW);

        __syncthreads();   // pairs with rec init sync

        #pragma unroll 1
        for (int blk = 0; blk < 33; blk++) {
            if (blk > 0) {
                const int t0h = (blk - 1) * 16;
                const float* yr[4];
                #pragma unroll
                for (int r = 0; r < 4; r++)
                    yr[r] = myhist + (((t0h + r0 + r) & 31) * ST_ROW);

                ull acc[4][4];
                #pragma unroll
                for (int r = 0; r < 4; r++)
                    #pragma unroll
                    for (int c = 0; c < 4; c++) acc[r][c] = 0ULL;

                #pragma unroll 4
                for (int kp = 0; kp < 64; kp++) {
                    const int off = (kp < 32) ? (2*kp) : (68 + 2*(kp-32));
                    ulonglong2 wc0 = *(const ulonglong2*)(WcP + kp*64 + c4);
                    ulonglong2 wc1 = *(const ulonglong2*)(WcP + kp*64 + c4 + 2);
                    #pragma unroll
                    for (int r = 0; r < 4; r++) {
                        ull yv = *(const ull*)(yr[r] + off);
                        acc[r][0] = ffma2(yv, wc0.x, acc[r][0]);
                        acc[r][1] = ffma2(yv, wc0.y, acc[r][1]);
                        acc[r][2] = ffma2(yv, wc1.x, acc[r][2]);
                        acc[r][3] = ffma2(yv, wc1.y, acc[r][3]);
                    }
                }

                #pragma unroll
                for (int r = 0; r < 4; r++) {
                    float4 o; float x, y;
                    upk2(acc[r][0], x, y); o.x = x + y + bb[0];
                    upk2(acc[r][1], x, y); o.y = x + y + bb[1];
                    upk2(acc[r][2], x, y); o.z = x + y + bb[2];
                    upk2(acc[r][3], x, y); o.w = x + y + bb[3];
                    *(float4*)(out + ((size_t)b * T_ + t0h + r0 + r) * 64 + c4) = o;
                }
            }
            __syncthreads();   // block boundary (all 384)
        }
    }
}

extern "C" void kernel_launch(void* const* d_in, const int* in_sizes, int n_in,
                              void* d_out, int out_size) {
    (void)in_sizes; (void)n_in; (void)out_size;
    const float* X  = (const float*)d_in[0];
    const float* W1 = (const float*)d_in[1];
    const float* b1 = (const float*)d_in[2];
    const float* W2 = (const float*)d_in[3];
    const float* b2 = (const float*)d_in[4];
    const float* Wc = (const float*)d_in[5];
    const float* bc = (const float*)d_in[6];
    float* out = (float*)d_out;

    cudaFuncSetAttribute(k1_in_gemm, cudaFuncAttributeMaxDynamicSharedMemorySize, 98304);
    cudaFuncSetAttribute(k2_fused,   cudaFuncAttributeMaxDynamicSharedMemorySize, 98304);

    k1_in_gemm<<<M_/64, 256, 98304>>>(X, W1, b1);

    const int k2_smem = (8192 + 2*32*ST_ROW) * 4;   // WcP + history ring
    k2_fused<<<B_/2, 384, k2_smem>>>(W2, b2, Wc, bc, out);
}